// round 8
// baseline (speedup 1.0000x reference)
#include <cuda_runtime.h>
#include <cuda_bf16.h>
#include <cstdint>

// Problem constants
#define BB 8
#define CC 256
#define CI 128
#define NN 4096          // H*W
#define MM 1024          // (H/2)*(W/2)
#define BN_EPS 1e-5f

// ---------------------------------------------------------------------------
// Scratch (static __device__ allocations only)
// ---------------------------------------------------------------------------
__device__ float d_S[(size_t)BB * NN * MM];       // raw attention scores [b][q][m]
__device__ float d_PHI[(size_t)BB * NN * CI];     // phi full-res [n][ci] fp32
__device__ float d_G[(size_t)BB * CI * NN];       // g full-res [c][n] fp32
__device__ float d_WY[(size_t)BB * CC * NN];      // W conv output (pre-BN) [o][n]
__device__ float d_bcat[384];                     // theta|phi|g biases
__device__ double d_sum[CC];
__device__ double d_sq[CC];
__device__ float d_scale[CC];
__device__ float d_shift[CC];
// hi/lo bf16 split operands
__device__ __nv_bfloat16 d_XTh[(size_t)BB * NN * CC];  // x^T [b][n][c]
__device__ __nv_bfloat16 d_XTl[(size_t)BB * NN * CC];
__device__ __nv_bfloat16 d_TPWh[256 * CC];             // theta(0:128)|phi(128:256) weights
__device__ __nv_bfloat16 d_TPWl[256 * CC];
__device__ __nv_bfloat16 d_GWh[CI * CC];               // g weights
__device__ __nv_bfloat16 d_GWl[CI * CC];
__device__ __nv_bfloat16 d_WWh[CC * CI];               // W weights
__device__ __nv_bfloat16 d_WWl[CC * CI];
__device__ __nv_bfloat16 d_Th[(size_t)BB * NN * CI];   // theta [b][n][ci]
__device__ __nv_bfloat16 d_Tl[(size_t)BB * NN * CI];
__device__ __nv_bfloat16 d_PHh[(size_t)BB * MM * CI];  // pooled phi [b][m][ci]
__device__ __nv_bfloat16 d_PHl[(size_t)BB * MM * CI];
__device__ __nv_bfloat16 d_Gh[(size_t)BB * CI * MM];   // pooled g [b][c][m]
__device__ __nv_bfloat16 d_Gl[(size_t)BB * CI * MM];
__device__ __nv_bfloat16 d_Ph[(size_t)BB * NN * MM];   // probs [b][q][m]
__device__ __nv_bfloat16 d_Pl[(size_t)BB * NN * MM];
__device__ __nv_bfloat16 d_Yh[(size_t)BB * NN * CI];   // attention out [b][n][ci]
__device__ __nv_bfloat16 d_Yl[(size_t)BB * NN * CI];

// ---------------------------------------------------------------------------
// mma.sync helpers (baseline PTX, plain sm_103 target)
// ---------------------------------------------------------------------------
__device__ __forceinline__ uint32_t smem_u32(const void* p) {
  uint32_t a;
  asm("{ .reg .u64 t; cvta.to.shared.u64 t, %1; cvt.u32.u64 %0, t; }" : "=r"(a) : "l"(p));
  return a;
}
__device__ __forceinline__ void ldm_x4(uint32_t* r, uint32_t addr) {
  asm volatile("ldmatrix.sync.aligned.m8n8.x4.shared.b16 {%0,%1,%2,%3}, [%4];"
               : "=r"(r[0]), "=r"(r[1]), "=r"(r[2]), "=r"(r[3]) : "r"(addr));
}
__device__ __forceinline__ void mma_bf16(float* c, const uint32_t* a, uint32_t b0, uint32_t b1) {
  asm volatile(
      "mma.sync.aligned.m16n8k16.row.col.f32.bf16.bf16.f32 "
      "{%0,%1,%2,%3}, {%4,%5,%6,%7}, {%8,%9}, {%0,%1,%2,%3};"
      : "+f"(c[0]), "+f"(c[1]), "+f"(c[2]), "+f"(c[3])
      : "r"(a[0]), "r"(a[1]), "r"(a[2]), "r"(a[3]), "r"(b0), "r"(b1));
}
__device__ __forceinline__ void split2(float a, float b, __nv_bfloat162& h, __nv_bfloat162& l) {
  __nv_bfloat16 h0 = __float2bfloat16_rn(a), h1 = __float2bfloat16_rn(b);
  __nv_bfloat16 l0 = __float2bfloat16_rn(a - __bfloat162float(h0));
  __nv_bfloat16 l1 = __float2bfloat16_rn(b - __bfloat162float(h1));
  h = __halves2bfloat162(h0, h1);
  l = __halves2bfloat162(l0, l1);
}

// smem tile: 128 rows x 64 bf16, padded row stride 72 elems (272B)
#define TPAD 72
#define TILE_ELEMS (128 * TPAD)
#define DSMEM_BYTES (4 * TILE_ELEMS * 2)  // 73728

__device__ __forceinline__ void load_tile(__nv_bfloat16* s, const __nv_bfloat16* g,
                                          int gstride, int tid) {
#pragma unroll
  for (int i = 0; i < 4; i++) {
    int idx = tid + i * 256;
    int row = idx >> 3, c4 = idx & 7;
    *(uint4*)&s[row * TPAD + c4 * 8] = *(const uint4*)&g[(size_t)row * gstride + c4 * 8];
  }
}

// Warp-level 128x128 GEMM over one 64-wide k-chunk in smem. Hi/lo split: 3 terms.
__device__ __forceinline__ void chunk_mma(uint32_t sAh, uint32_t sAl, uint32_t sBh,
                                          uint32_t sBl, int wm, int wn, int lane,
                                          float (&C)[2][8][4]) {
  const int ar = wm * 32 + (lane & 15);
  const int ac = (lane >> 4) * 8;
  const int bg = lane >> 3;
  const int br = wn * 64 + ((bg & 2) << 2) + (lane & 7);
  const int bc = (bg & 1) << 3;
#pragma unroll
  for (int kk = 0; kk < 4; kk++) {
    uint32_t Ah[2][4], Al[2][4], Bh[4][4], Bl[4][4];
    uint32_t aoff = ((ar) * TPAD + kk * 16 + ac) * 2;
    ldm_x4(Ah[0], sAh + aoff);
    ldm_x4(Ah[1], sAh + aoff + 16 * TPAD * 2);
    ldm_x4(Al[0], sAl + aoff);
    ldm_x4(Al[1], sAl + aoff + 16 * TPAD * 2);
#pragma unroll
    for (int p = 0; p < 4; p++) {
      uint32_t boff = ((br + p * 16) * TPAD + kk * 16 + bc) * 2;
      ldm_x4(Bh[p], sBh + boff);
      ldm_x4(Bl[p], sBl + boff);
    }
#pragma unroll
    for (int mi = 0; mi < 2; mi++)
#pragma unroll
      for (int p = 0; p < 4; p++)
#pragma unroll
        for (int h = 0; h < 2; h++) {
          float* acc = C[mi][p * 2 + h];
          mma_bf16(acc, Ah[mi], Bh[p][h * 2], Bh[p][h * 2 + 1]);
          mma_bf16(acc, Ah[mi], Bl[p][h * 2], Bl[p][h * 2 + 1]);
          mma_bf16(acc, Al[mi], Bh[p][h * 2], Bh[p][h * 2 + 1]);
        }
  }
}

// Shared smem declaration pattern for all HMMA kernels
#define MMA_PROLOGUE                                              \
  extern __shared__ __align__(16) __nv_bfloat16 dsm[];            \
  __nv_bfloat16* Ah = dsm;                                        \
  __nv_bfloat16* Al = dsm + TILE_ELEMS;                           \
  __nv_bfloat16* Bh = dsm + 2 * TILE_ELEMS;                       \
  __nv_bfloat16* Bl = dsm + 3 * TILE_ELEMS;                       \
  const int tid = threadIdx.x, wid = tid >> 5, lane = tid & 31;   \
  const int wm = wid >> 1, wn = wid & 1;                          \
  const uint32_t sAh = smem_u32(Ah), sAl = smem_u32(Al);          \
  const uint32_t sBh = smem_u32(Bh), sBl = smem_u32(Bl);          \
  float C[2][8][4] = {};

// ---------------------------------------------------------------------------
// init: split all weights to hi/lo bf16, pack biases, zero BN accumulators
// ---------------------------------------------------------------------------
__global__ __launch_bounds__(256) void init_kernel(
    const float* __restrict__ tw, const float* __restrict__ tb,
    const float* __restrict__ pw, const float* __restrict__ pb,
    const float* __restrict__ gw, const float* __restrict__ gb,
    const float* __restrict__ Ww) {
  int idx = blockIdx.x * 256 + threadIdx.x;
  if (idx < CC) { d_sum[idx] = 0.0; d_sq[idx] = 0.0; }
  if (idx < 384)
    d_bcat[idx] = (idx < 128) ? tb[idx] : (idx < 256) ? pb[idx - 128] : gb[idx - 256];
  float v;
  __nv_bfloat16 h;
  if (idx < 65536) {  // theta|phi weights [256][256]
    v = (idx < 32768) ? tw[idx] : pw[idx - 32768];
    h = __float2bfloat16_rn(v);
    d_TPWh[idx] = h;
    d_TPWl[idx] = __float2bfloat16_rn(v - __bfloat162float(h));
  } else if (idx < 98304) {  // g weights [128][256]
    int j = idx - 65536;
    v = gw[j];
    h = __float2bfloat16_rn(v);
    d_GWh[j] = h;
    d_GWl[j] = __float2bfloat16_rn(v - __bfloat162float(h));
  } else if (idx < 131072) {  // W weights [256][128]
    int j = idx - 98304;
    v = Ww[j];
    h = __float2bfloat16_rn(v);
    d_WWh[j] = h;
    d_WWl[j] = __float2bfloat16_rn(v - __bfloat162float(h));
  }
}

// ---------------------------------------------------------------------------
// xsplit: transpose x [c][n] -> x^T hi/lo bf16 [n][c]
// ---------------------------------------------------------------------------
__global__ void xsplit_kernel(const float* __restrict__ x) {  // (32,32), grid (128,8,8)
  __shared__ float t[32][33];
  int b = blockIdx.z, c0 = blockIdx.y * 32, n0 = blockIdx.x * 32;
  int tx = threadIdx.x, ty = threadIdx.y;
  t[ty][tx] = x[((size_t)b * CC + c0 + ty) * NN + n0 + tx];
  __syncthreads();
  float v = t[tx][ty];
  size_t o = ((size_t)b * NN + n0 + ty) * CC + c0 + tx;
  __nv_bfloat16 h = __float2bfloat16_rn(v);
  d_XTh[o] = h;
  d_XTl[o] = __float2bfloat16_rn(v - __bfloat162float(h));
}

// ---------------------------------------------------------------------------
// conv_tp: D[n][w] = x^T @ (theta|phi)_w^T + bias. grid (32 n, 2 w, 8 b)
// y=0: theta -> hi/lo bf16 [n][ci]. y=1: phi -> fp32 [n][ci].
// ---------------------------------------------------------------------------
__global__ __launch_bounds__(256) void conv_tp_kernel() {
  MMA_PROLOGUE
  const int b = blockIdx.z, n0 = blockIdx.x * 128, w0 = blockIdx.y * 128;
  const __nv_bfloat16* gAh = d_XTh + ((size_t)b * NN + n0) * CC;
  const __nv_bfloat16* gAl = d_XTl + ((size_t)b * NN + n0) * CC;
  const __nv_bfloat16* gBh = d_TPWh + (size_t)w0 * CC;
  const __nv_bfloat16* gBl = d_TPWl + (size_t)w0 * CC;
#pragma unroll
  for (int k0 = 0; k0 < CC; k0 += 64) {
    load_tile(Ah, gAh + k0, CC, tid);
    load_tile(Al, gAl + k0, CC, tid);
    load_tile(Bh, gBh + k0, CC, tid);
    load_tile(Bl, gBl + k0, CC, tid);
    __syncthreads();
    chunk_mma(sAh, sAl, sBh, sBl, wm, wn, lane, C);
    __syncthreads();
  }
  const int nbase = n0 + wm * 32 + (lane >> 2);
  const int wbase = wn * 64 + (lane & 3) * 2;
#pragma unroll
  for (int mi = 0; mi < 2; mi++)
#pragma unroll
    for (int nj = 0; nj < 8; nj++) {
      int n = nbase + mi * 16;
      int w = wbase + nj * 8;
      float b0v = d_bcat[w0 + w], b1v = d_bcat[w0 + w + 1];
      float v00 = C[mi][nj][0] + b0v, v01 = C[mi][nj][1] + b1v;
      float v10 = C[mi][nj][2] + b0v, v11 = C[mi][nj][3] + b1v;
      if (blockIdx.y == 0) {
        __nv_bfloat162 h, l;
        split2(v00, v01, h, l);
        *(__nv_bfloat162*)&d_Th[((size_t)b * NN + n) * CI + w] = h;
        *(__nv_bfloat162*)&d_Tl[((size_t)b * NN + n) * CI + w] = l;
        split2(v10, v11, h, l);
        *(__nv_bfloat162*)&d_Th[((size_t)b * NN + n + 8) * CI + w] = h;
        *(__nv_bfloat162*)&d_Tl[((size_t)b * NN + n + 8) * CI + w] = l;
      } else {
        *(float2*)&d_PHI[((size_t)b * NN + n) * CI + w] = make_float2(v00, v01);
        *(float2*)&d_PHI[((size_t)b * NN + n + 8) * CI + w] = make_float2(v10, v11);
      }
    }
}

// ---------------------------------------------------------------------------
// conv_g: D[c][n] = g_w @ x + bias (fp32). grid (32 n, 1, 8 b)
// ---------------------------------------------------------------------------
__global__ __launch_bounds__(256) void conv_g_kernel() {
  MMA_PROLOGUE
  const int b = blockIdx.z, n0 = blockIdx.x * 128;
  const __nv_bfloat16* gAh = d_GWh;
  const __nv_bfloat16* gAl = d_GWl;
  const __nv_bfloat16* gBh = d_XTh + ((size_t)b * NN + n0) * CC;
  const __nv_bfloat16* gBl = d_XTl + ((size_t)b * NN + n0) * CC;
#pragma unroll
  for (int k0 = 0; k0 < CC; k0 += 64) {
    load_tile(Ah, gAh + k0, CC, tid);
    load_tile(Al, gAl + k0, CC, tid);
    load_tile(Bh, gBh + k0, CC, tid);
    load_tile(Bl, gBl + k0, CC, tid);
    __syncthreads();
    chunk_mma(sAh, sAl, sBh, sBl, wm, wn, lane, C);
    __syncthreads();
  }
  const int cbase = wm * 32 + (lane >> 2);
  const int nbase = n0 + wn * 64 + (lane & 3) * 2;
#pragma unroll
  for (int mi = 0; mi < 2; mi++)
#pragma unroll
    for (int nj = 0; nj < 8; nj++) {
      int c = cbase + mi * 16;
      int n = nbase + nj * 8;
      float g0 = d_bcat[256 + c], g8 = d_bcat[256 + c + 8];
      *(float2*)&d_G[((size_t)b * CI + c) * NN + n] =
          make_float2(C[mi][nj][0] + g0, C[mi][nj][1] + g0);
      *(float2*)&d_G[((size_t)b * CI + c + 8) * NN + n] =
          make_float2(C[mi][nj][2] + g8, C[mi][nj][3] + g8);
    }
}

// ---------------------------------------------------------------------------
// pool_phi: [n][ci] fp32 -> pooled [m][ci] hi/lo bf16 (coalesced along ci)
// ---------------------------------------------------------------------------
__global__ __launch_bounds__(256) void pool_phi_kernel() {
  int idx = blockIdx.x * 256 + threadIdx.x;  // over 8*1024*128
  int c = idx & 127;
  int m = (idx >> 7) & 1023;
  int b = idx >> 17;
  int n1 = (m >> 5) * 128 + (m & 31) * 2;
  const float* p = d_PHI + ((size_t)b * NN + n1) * CI + c;
  float v = fmaxf(fmaxf(p[0], p[CI]), fmaxf(p[64 * CI], p[65 * CI]));
  __nv_bfloat16 h = __float2bfloat16_rn(v);
  size_t o = ((size_t)b * MM + m) * CI + c;
  d_PHh[o] = h;
  d_PHl[o] = __float2bfloat16_rn(v - __bfloat162float(h));
}

// ---------------------------------------------------------------------------
// pool_g: [c][n] fp32 -> pooled [c][m] hi/lo bf16 (coalesced along m)
// ---------------------------------------------------------------------------
__global__ __launch_bounds__(256) void pool_g_kernel() {
  int idx = blockIdx.x * 256 + threadIdx.x;  // over 8*128*1024
  int m = idx & 1023;
  int c = (idx >> 10) & 127;
  int b = idx >> 17;
  int n1 = (m >> 5) * 128 + (m & 31) * 2;
  const float* p = d_G + ((size_t)b * CI + c) * NN + n1;
  float v = fmaxf(fmaxf(p[0], p[1]), fmaxf(p[64], p[65]));
  __nv_bfloat16 h = __float2bfloat16_rn(v);
  size_t o = ((size_t)b * CI + c) * MM + m;
  d_Gh[o] = h;
  d_Gl[o] = __float2bfloat16_rn(v - __bfloat162float(h));
}

// ---------------------------------------------------------------------------
// s_mma: S[b][q][m] = theta phi^T. A=theta (rows q), B=phi (rows m). grid (8,32,8)
// ---------------------------------------------------------------------------
__global__ __launch_bounds__(256) void s_mma_kernel() {
  MMA_PROLOGUE
  const int b = blockIdx.z, q0 = blockIdx.y * 128, m0 = blockIdx.x * 128;
  const __nv_bfloat16* gAh = d_Th + ((size_t)b * NN + q0) * CI;
  const __nv_bfloat16* gAl = d_Tl + ((size_t)b * NN + q0) * CI;
  const __nv_bfloat16* gBh = d_PHh + ((size_t)b * MM + m0) * CI;
  const __nv_bfloat16* gBl = d_PHl + ((size_t)b * MM + m0) * CI;
#pragma unroll
  for (int k0 = 0; k0 < CI; k0 += 64) {
    load_tile(Ah, gAh + k0, CI, tid);
    load_tile(Al, gAl + k0, CI, tid);
    load_tile(Bh, gBh + k0, CI, tid);
    load_tile(Bl, gBl + k0, CI, tid);
    __syncthreads();
    chunk_mma(sAh, sAl, sBh, sBl, wm, wn, lane, C);
    __syncthreads();
  }
  float* Sb = d_S + (size_t)b * NN * MM;
  const int qbase = q0 + wm * 32 + (lane >> 2);
  const int mbase = m0 + wn * 64 + (lane & 3) * 2;
#pragma unroll
  for (int mi = 0; mi < 2; mi++)
#pragma unroll
    for (int nj = 0; nj < 8; nj++) {
      int q = qbase + mi * 16;
      int m = mbase + nj * 8;
      *(float2*)&Sb[(size_t)q * MM + m] = make_float2(C[mi][nj][0], C[mi][nj][1]);
      *(float2*)&Sb[(size_t)(q + 8) * MM + m] = make_float2(C[mi][nj][2], C[mi][nj][3]);
    }
}

// ---------------------------------------------------------------------------
// softmax over M=1024, writes hi/lo bf16 probabilities
// ---------------------------------------------------------------------------
__global__ __launch_bounds__(128) void softmax_kernel() {
  const float* row = d_S + (size_t)blockIdx.x * MM;
  const int t = threadIdx.x;
  float4 v0 = *(const float4*)&row[t * 8];
  float4 v1 = *(const float4*)&row[t * 8 + 4];
  float mx = fmaxf(fmaxf(fmaxf(v0.x, v0.y), fmaxf(v0.z, v0.w)),
                   fmaxf(fmaxf(v1.x, v1.y), fmaxf(v1.z, v1.w)));
  __shared__ float red[4];
#pragma unroll
  for (int o = 16; o; o >>= 1) mx = fmaxf(mx, __shfl_xor_sync(0xffffffffu, mx, o));
  if ((t & 31) == 0) red[t >> 5] = mx;
  __syncthreads();
  mx = fmaxf(fmaxf(red[0], red[1]), fmaxf(red[2], red[3]));
  v0.x = __expf(v0.x - mx); v0.y = __expf(v0.y - mx);
  v0.z = __expf(v0.z - mx); v0.w = __expf(v0.w - mx);
  v1.x = __expf(v1.x - mx); v1.y = __expf(v1.y - mx);
  v1.z = __expf(v1.z - mx); v1.w = __expf(v1.w - mx);
  float s = v0.x + v0.y + v0.z + v0.w + v1.x + v1.y + v1.z + v1.w;
  __syncthreads();
#pragma unroll
  for (int o = 16; o; o >>= 1) s += __shfl_xor_sync(0xffffffffu, s, o);
  if ((t & 31) == 0) red[t >> 5] = s;
  __syncthreads();
  float inv = 1.0f / (red[0] + red[1] + red[2] + red[3]);
  float p[8] = {v0.x * inv, v0.y * inv, v0.z * inv, v0.w * inv,
                v1.x * inv, v1.y * inv, v1.z * inv, v1.w * inv};
  size_t base = (size_t)blockIdx.x * MM + t * 8;
  __nv_bfloat16 hbuf[8], lbuf[8];
#pragma unroll
  for (int j = 0; j < 8; j++) {
    __nv_bfloat16 h = __float2bfloat16_rn(p[j]);
    hbuf[j] = h;
    lbuf[j] = __float2bfloat16_rn(p[j] - __bfloat162float(h));
  }
  *(uint4*)&d_Ph[base] = *(uint4*)hbuf;
  *(uint4*)&d_Pl[base] = *(uint4*)lbuf;
}

// ---------------------------------------------------------------------------
// y_mma: Y[q][c] = P @ g^T. A=P (rows q), B=g (rows c, K=m). grid (32,1,8)
// Epilogue writes hi/lo bf16 Y [n][ci]
// ---------------------------------------------------------------------------
__global__ __launch_bounds__(256) void y_mma_kernel() {
  MMA_PROLOGUE
  const int b = blockIdx.z, q0 = blockIdx.x * 128;
  const __nv_bfloat16* gAh = d_Ph + ((size_t)b * NN + q0) * MM;
  const __nv_bfloat16* gAl = d_Pl + ((size_t)b * NN + q0) * MM;
  const __nv_bfloat16* gBh = d_Gh + (size_t)b * CI * MM;
  const __nv_bfloat16* gBl = d_Gl + (size_t)b * CI * MM;
  for (int k0 = 0; k0 < MM; k0 += 64) {
    load_tile(Ah, gAh + k0, MM, tid);
    load_tile(Al, gAl + k0, MM, tid);
    load_tile(Bh, gBh + k0, MM, tid);
    load_tile(Bl, gBl + k0, MM, tid);
    __syncthreads();
    chunk_mma(sAh, sAl, sBh, sBl, wm, wn, lane, C);
    __syncthreads();
  }
  const int qbase = q0 + wm * 32 + (lane >> 2);
  const int cbase = wn * 64 + (lane & 3) * 2;
#pragma unroll
  for (int mi = 0; mi < 2; mi++)
#pragma unroll
    for (int nj = 0; nj < 8; nj++) {
      int q = qbase + mi * 16;
      int c = cbase + nj * 8;
      __nv_bfloat162 h, l;
      split2(C[mi][nj][0], C[mi][nj][1], h, l);
      *(__nv_bfloat162*)&d_Yh[((size_t)b * NN + q) * CI + c] = h;
      *(__nv_bfloat162*)&d_Yl[((size_t)b * NN + q) * CI + c] = l;
      split2(C[mi][nj][2], C[mi][nj][3], h, l);
      *(__nv_bfloat162*)&d_Yh[((size_t)b * NN + q + 8) * CI + c] = h;
      *(__nv_bfloat162*)&d_Yl[((size_t)b * NN + q + 8) * CI + c] = l;
    }
}

// ---------------------------------------------------------------------------
// wconv: WY[o][n] = W_w @ Y^T + W_b, + BN stats. A=W_w (rows o), B=Y (rows n).
// grid (32 n, 2 o, 8 b). K=128 -> 2 chunks.
// ---------------------------------------------------------------------------
__global__ __launch_bounds__(256) void wconv_mma_kernel(const float* __restrict__ Wb) {
  MMA_PROLOGUE
  __shared__ float s_sum[128];
  __shared__ float s_sq[128];
  const int b = blockIdx.z, n0 = blockIdx.x * 128, o0 = blockIdx.y * 128;
  if (tid < 128) { s_sum[tid] = 0.f; s_sq[tid] = 0.f; }
  const __nv_bfloat16* gAh = d_WWh + (size_t)o0 * CI;
  const __nv_bfloat16* gAl = d_WWl + (size_t)o0 * CI;
  const __nv_bfloat16* gBh = d_Yh + ((size_t)b * NN + n0) * CI;
  const __nv_bfloat16* gBl = d_Yl + ((size_t)b * NN + n0) * CI;
#pragma unroll
  for (int k0 = 0; k0 < CI; k0 += 64) {
    load_tile(Ah, gAh + k0, CI, tid);
    load_tile(Al, gAl + k0, CI, tid);
    load_tile(Bh, gBh + k0, CI, tid);
    load_tile(Bl, gBl + k0, CI, tid);
    __syncthreads();
    chunk_mma(sAh, sAl, sBh, sBl, wm, wn, lane, C);
    __syncthreads();
  }
  const int orow0 = wm * 32 + (lane >> 2);
  const int nbase = n0 + wn * 64 + (lane & 3) * 2;
  float ls[2][2] = {}, lq[2][2] = {};
  float* WYb = d_WY + (size_t)b * CC * NN;
#pragma unroll
  for (int mi = 0; mi < 2; mi++) {
    int o = o0 + orow0 + mi * 16;
    float bias0 = Wb[o], bias8 = Wb[o + 8];
#pragma unroll
    for (int nj = 0; nj < 8; nj++) {
      int n = nbase + nj * 8;
      float v0 = C[mi][nj][0] + bias0, v1 = C[mi][nj][1] + bias0;
      float v2 = C[mi][nj][2] + bias8, v3 = C[mi][nj][3] + bias8;
      ls[mi][0] += v0 + v1;
      lq[mi][0] += v0 * v0 + v1 * v1;
      ls[mi][1] += v2 + v3;
      lq[mi][1] += v2 * v2 + v3 * v3;
      *(float2*)&WYb[(size_t)o * NN + n] = make_float2(v0, v1);
      *(float2*)&WYb[(size_t)(o + 8) * NN + n] = make_float2(v2, v3);
    }
  }
#pragma unroll
  for (int mi = 0; mi < 2; mi++)
#pragma unroll
    for (int h = 0; h < 2; h++) {
      int orow = orow0 + mi * 16 + h * 8;
      atomicAdd(&s_sum[orow], ls[mi][h]);
      atomicAdd(&s_sq[orow], lq[mi][h]);
    }
  __syncthreads();
  if (tid < 128) {
    atomicAdd(&d_sum[o0 + tid], (double)s_sum[tid]);
    atomicAdd(&d_sq[o0 + tid], (double)s_sq[tid]);
  }
}

// ---------------------------------------------------------------------------
// BN finalize
// ---------------------------------------------------------------------------
__global__ void bnprep_kernel(const float* __restrict__ gamma,
                              const float* __restrict__ beta) {
  int o = threadIdx.x;
  double cnt = (double)BB * (double)NN;
  double mean = d_sum[o] / cnt;
  double var = d_sq[o] / cnt - mean * mean;
  float sc = gamma[o] * rsqrtf((float)var + BN_EPS);
  d_scale[o] = sc;
  d_shift[o] = beta[o] - (float)mean * sc;
}

// ---------------------------------------------------------------------------
// final: out = WY*scale + shift + x
// ---------------------------------------------------------------------------
__global__ __launch_bounds__(256) void final_kernel(const float* __restrict__ x,
                                                    float* __restrict__ out) {
  size_t i4 = (size_t)blockIdx.x * 256 + threadIdx.x;
  int o = (int)((i4 >> 10) & 255);
  float sc = d_scale[o], sh = d_shift[o];
  float4 w = ((const float4*)d_WY)[i4];
  float4 xi = ((const float4*)x)[i4];
  float4 r;
  r.x = w.x * sc + sh + xi.x;
  r.y = w.y * sc + sh + xi.y;
  r.z = w.z * sc + sh + xi.z;
  r.w = w.w * sc + sh + xi.w;
  ((float4*)out)[i4] = r;
}

// ---------------------------------------------------------------------------
// launch
// ---------------------------------------------------------------------------
extern "C" void kernel_launch(void* const* d_in, const int* in_sizes, int n_in,
                              void* d_out, int out_size) {
  const float* x  = (const float*)d_in[0];
  const float* tw = (const float*)d_in[1];
  const float* tb = (const float*)d_in[2];
  const float* pw = (const float*)d_in[3];
  const float* pb = (const float*)d_in[4];
  const float* gw = (const float*)d_in[5];
  const float* gb = (const float*)d_in[6];
  const float* Ww = (const float*)d_in[7];
  const float* Wb = (const float*)d_in[8];
  const float* bg = (const float*)d_in[9];
  const float* bb = (const float*)d_in[10];
  float* out = (float*)d_out;

  cudaFuncSetAttribute(conv_tp_kernel, cudaFuncAttributeMaxDynamicSharedMemorySize, DSMEM_BYTES);
  cudaFuncSetAttribute(conv_g_kernel, cudaFuncAttributeMaxDynamicSharedMemorySize, DSMEM_BYTES);
  cudaFuncSetAttribute(s_mma_kernel, cudaFuncAttributeMaxDynamicSharedMemorySize, DSMEM_BYTES);
  cudaFuncSetAttribute(y_mma_kernel, cudaFuncAttributeMaxDynamicSharedMemorySize, DSMEM_BYTES);
  cudaFuncSetAttribute(wconv_mma_kernel, cudaFuncAttributeMaxDynamicSharedMemorySize, DSMEM_BYTES);

  init_kernel<<<512, 256>>>(tw, tb, pw, pb, gw, gb, Ww);
  xsplit_kernel<<<dim3(128, 8, BB), dim3(32, 32)>>>(x);
  conv_tp_kernel<<<dim3(32, 2, BB), 256, DSMEM_BYTES>>>();
  conv_g_kernel<<<dim3(32, 1, BB), 256, DSMEM_BYTES>>>();
  pool_phi_kernel<<<(BB * MM * CI) / 256, 256>>>();
  pool_g_kernel<<<(BB * CI * MM) / 256, 256>>>();
  s_mma_kernel<<<dim3(8, 32, BB), 256, DSMEM_BYTES>>>();
  softmax_kernel<<<BB * NN, 128>>>();
  y_mma_kernel<<<dim3(32, 1, BB), 256, DSMEM_BYTES>>>();
  wconv_mma_kernel<<<dim3(32, 2, BB), 256, DSMEM_BYTES>>>(Wb);
  bnprep_kernel<<<1, 256>>>(bg, bb);
  final_kernel<<<(BB * CC * NN / 4) / 256, 256>>>(x, out);
}

// round 9
// speedup vs baseline: 1.4767x; 1.4767x over previous
#include <cuda_runtime.h>
#include <cuda_bf16.h>
#include <cstdint>

// Problem constants
#define BB 8
#define CC 256
#define CI 128
#define NN 4096          // H*W
#define MM 1024          // (H/2)*(W/2)
#define BN_EPS 1e-5f

// ---------------------------------------------------------------------------
// Scratch (static __device__ allocations only)
// ---------------------------------------------------------------------------
__device__ float d_S[(size_t)BB * NN * MM];       // raw attention scores [b][q][m]
__device__ float d_PHI[(size_t)BB * NN * CI];     // phi full-res [n][ci] fp32
__device__ float d_G[(size_t)BB * CI * NN];       // g full-res [c][n] fp32
__device__ float d_WY[(size_t)BB * CC * NN];      // W conv output (pre-BN) [o][n]
__device__ float d_bcat[384];                     // theta|phi|g biases
__device__ double d_sum[CC];
__device__ double d_sq[CC];
__device__ float d_scale[CC];
__device__ float d_shift[CC];
// hi/lo bf16 split operands
__device__ __nv_bfloat16 d_XTh[(size_t)BB * NN * CC];  // x^T [b][n][c]
__device__ __nv_bfloat16 d_XTl[(size_t)BB * NN * CC];
__device__ __nv_bfloat16 d_TPWh[256 * CC];             // theta(0:128)|phi(128:256) weights
__device__ __nv_bfloat16 d_TPWl[256 * CC];
__device__ __nv_bfloat16 d_GWh[CI * CC];               // g weights
__device__ __nv_bfloat16 d_GWl[CI * CC];
__device__ __nv_bfloat16 d_WWh[CC * CI];               // W weights
__device__ __nv_bfloat16 d_WWl[CC * CI];
__device__ __nv_bfloat16 d_Th[(size_t)BB * NN * CI];   // theta [b][n][ci]
__device__ __nv_bfloat16 d_Tl[(size_t)BB * NN * CI];
__device__ __nv_bfloat16 d_PHh[(size_t)BB * MM * CI];  // pooled phi [b][m][ci]
__device__ __nv_bfloat16 d_PHl[(size_t)BB * MM * CI];
__device__ __nv_bfloat16 d_Gh[(size_t)BB * CI * MM];   // pooled g [b][c][m]
__device__ __nv_bfloat16 d_Gl[(size_t)BB * CI * MM];
__device__ __nv_bfloat16 d_Ph[(size_t)BB * NN * MM];   // probs [b][q][m]
__device__ __nv_bfloat16 d_Pl[(size_t)BB * NN * MM];
__device__ __nv_bfloat16 d_Yh[(size_t)BB * NN * CI];   // attention out [b][n][ci]
__device__ __nv_bfloat16 d_Yl[(size_t)BB * NN * CI];

// ---------------------------------------------------------------------------
// mma.sync + cp.async helpers (baseline PTX, plain sm_103 target)
// ---------------------------------------------------------------------------
__device__ __forceinline__ uint32_t smem_u32(const void* p) {
  uint32_t a;
  asm("{ .reg .u64 t; cvta.to.shared.u64 t, %1; cvt.u32.u64 %0, t; }" : "=r"(a) : "l"(p));
  return a;
}
__device__ __forceinline__ void ldm_x4(uint32_t* r, uint32_t addr) {
  asm volatile("ldmatrix.sync.aligned.m8n8.x4.shared.b16 {%0,%1,%2,%3}, [%4];"
               : "=r"(r[0]), "=r"(r[1]), "=r"(r[2]), "=r"(r[3]) : "r"(addr));
}
__device__ __forceinline__ void mma_bf16(float* c, const uint32_t* a, uint32_t b0, uint32_t b1) {
  asm volatile(
      "mma.sync.aligned.m16n8k16.row.col.f32.bf16.bf16.f32 "
      "{%0,%1,%2,%3}, {%4,%5,%6,%7}, {%8,%9}, {%0,%1,%2,%3};"
      : "+f"(c[0]), "+f"(c[1]), "+f"(c[2]), "+f"(c[3])
      : "r"(a[0]), "r"(a[1]), "r"(a[2]), "r"(a[3]), "r"(b0), "r"(b1));
}
__device__ __forceinline__ void cpa16(uint32_t dst, const void* src) {
  asm volatile("cp.async.cg.shared.global [%0], [%1], 16;" :: "r"(dst), "l"(src));
}
__device__ __forceinline__ void split2(float a, float b, __nv_bfloat162& h, __nv_bfloat162& l) {
  __nv_bfloat16 h0 = __float2bfloat16_rn(a), h1 = __float2bfloat16_rn(b);
  __nv_bfloat16 l0 = __float2bfloat16_rn(a - __bfloat162float(h0));
  __nv_bfloat16 l1 = __float2bfloat16_rn(b - __bfloat162float(h1));
  h = __halves2bfloat162(h0, h1);
  l = __halves2bfloat162(l0, l1);
}

// smem tile: 128 rows x 64 bf16, padded row stride 72 elems (272B)
#define TPAD 72
#define TILE_ELEMS (128 * TPAD)
#define TILE_BYTES (TILE_ELEMS * 2)
#define STAGE_BYTES (4 * TILE_BYTES)
#define DSMEM_BYTES (2 * STAGE_BYTES)  // 147456

__device__ __forceinline__ void load_tile_async(uint32_t sbase, const __nv_bfloat16* g,
                                                int gstride, int tid) {
#pragma unroll
  for (int i = 0; i < 4; i++) {
    int idx = tid + i * 256;
    int row = idx >> 3, c4 = idx & 7;
    cpa16(sbase + (uint32_t)(row * TPAD + c4 * 8) * 2,
          g + (size_t)row * gstride + c4 * 8);
  }
}

// Warp-level 128x128 GEMM over one 64-wide k-chunk in smem. Hi/lo split: 3 terms.
__device__ __forceinline__ void chunk_mma(uint32_t sAh, uint32_t sAl, uint32_t sBh,
                                          uint32_t sBl, int wm, int wn, int lane,
                                          float (&C)[2][8][4]) {
  const int ar = wm * 32 + (lane & 15);
  const int ac = (lane >> 4) * 8;
  const int bg = lane >> 3;
  const int br = wn * 64 + ((bg & 2) << 2) + (lane & 7);
  const int bc = (bg & 1) << 3;
#pragma unroll
  for (int kk = 0; kk < 4; kk++) {
    uint32_t Ah[2][4], Al[2][4], Bh[4][4], Bl[4][4];
    uint32_t aoff = ((ar) * TPAD + kk * 16 + ac) * 2;
    ldm_x4(Ah[0], sAh + aoff);
    ldm_x4(Ah[1], sAh + aoff + 16 * TPAD * 2);
    ldm_x4(Al[0], sAl + aoff);
    ldm_x4(Al[1], sAl + aoff + 16 * TPAD * 2);
#pragma unroll
    for (int p = 0; p < 4; p++) {
      uint32_t boff = ((br + p * 16) * TPAD + kk * 16 + bc) * 2;
      ldm_x4(Bh[p], sBh + boff);
      ldm_x4(Bl[p], sBl + boff);
    }
#pragma unroll
    for (int mi = 0; mi < 2; mi++)
#pragma unroll
      for (int p = 0; p < 4; p++)
#pragma unroll
        for (int h = 0; h < 2; h++) {
          float* acc = C[mi][p * 2 + h];
          mma_bf16(acc, Ah[mi], Bh[p][h * 2], Bh[p][h * 2 + 1]);
          mma_bf16(acc, Ah[mi], Bl[p][h * 2], Bl[p][h * 2 + 1]);
          mma_bf16(acc, Al[mi], Bh[p][h * 2], Bh[p][h * 2 + 1]);
        }
  }
}

// Double-buffered cp.async pipeline over NCH 64-wide k-chunks.
template <int NCH>
__device__ __forceinline__ void mma_pipeline(const __nv_bfloat16* gAh, const __nv_bfloat16* gAl,
                                             const __nv_bfloat16* gBh, const __nv_bfloat16* gBl,
                                             int sA, int sB, uint32_t sb, int tid,
                                             int wm, int wn, int lane, float (&C)[2][8][4]) {
  // stage s tiles at sb + s*STAGE_BYTES + {0,1,2,3}*TILE_BYTES
  {
    load_tile_async(sb, gAh, sA, tid);
    load_tile_async(sb + TILE_BYTES, gAl, sA, tid);
    load_tile_async(sb + 2 * TILE_BYTES, gBh, sB, tid);
    load_tile_async(sb + 3 * TILE_BYTES, gBl, sB, tid);
    asm volatile("cp.async.commit_group;");
  }
#pragma unroll 1
  for (int ch = 0; ch < NCH; ch++) {
    if (ch + 1 < NCH) {
      uint32_t nb = sb + ((ch + 1) & 1) * STAGE_BYTES;
      int ko = (ch + 1) * 64;
      load_tile_async(nb, gAh + ko, sA, tid);
      load_tile_async(nb + TILE_BYTES, gAl + ko, sA, tid);
      load_tile_async(nb + 2 * TILE_BYTES, gBh + ko, sB, tid);
      load_tile_async(nb + 3 * TILE_BYTES, gBl + ko, sB, tid);
      asm volatile("cp.async.commit_group;");
      asm volatile("cp.async.wait_group 1;");
    } else {
      asm volatile("cp.async.wait_group 0;");
    }
    __syncthreads();
    uint32_t cb = sb + (ch & 1) * STAGE_BYTES;
    chunk_mma(cb, cb + TILE_BYTES, cb + 2 * TILE_BYTES, cb + 3 * TILE_BYTES, wm, wn, lane, C);
    __syncthreads();
  }
}

#define MMA_PROLOGUE                                              \
  extern __shared__ __align__(16) __nv_bfloat16 dsm[];            \
  const uint32_t sb = smem_u32(dsm);                              \
  const int tid = threadIdx.x, wid = tid >> 5, lane = tid & 31;   \
  const int wm = wid >> 1, wn = wid & 1;                          \
  float C[2][8][4] = {};

// ---------------------------------------------------------------------------
// init: split all weights to hi/lo bf16, pack biases, zero BN accumulators
// ---------------------------------------------------------------------------
__global__ __launch_bounds__(256) void init_kernel(
    const float* __restrict__ tw, const float* __restrict__ tb,
    const float* __restrict__ pw, const float* __restrict__ pb,
    const float* __restrict__ gw, const float* __restrict__ gb,
    const float* __restrict__ Ww) {
  int idx = blockIdx.x * 256 + threadIdx.x;
  if (idx < CC) { d_sum[idx] = 0.0; d_sq[idx] = 0.0; }
  if (idx < 384)
    d_bcat[idx] = (idx < 128) ? tb[idx] : (idx < 256) ? pb[idx - 128] : gb[idx - 256];
  float v;
  __nv_bfloat16 h;
  if (idx < 65536) {  // theta|phi weights [256][256]
    v = (idx < 32768) ? tw[idx] : pw[idx - 32768];
    h = __float2bfloat16_rn(v);
    d_TPWh[idx] = h;
    d_TPWl[idx] = __float2bfloat16_rn(v - __bfloat162float(h));
  } else if (idx < 98304) {  // g weights [128][256]
    int j = idx - 65536;
    v = gw[j];
    h = __float2bfloat16_rn(v);
    d_GWh[j] = h;
    d_GWl[j] = __float2bfloat16_rn(v - __bfloat162float(h));
  } else if (idx < 131072) {  // W weights [256][128]
    int j = idx - 98304;
    v = Ww[j];
    h = __float2bfloat16_rn(v);
    d_WWh[j] = h;
    d_WWl[j] = __float2bfloat16_rn(v - __bfloat162float(h));
  }
}

// ---------------------------------------------------------------------------
// xsplit: transpose x [c][n] -> x^T hi/lo bf16 [n][c]
// ---------------------------------------------------------------------------
__global__ void xsplit_kernel(const float* __restrict__ x) {  // (32,32), grid (128,8,8)
  __shared__ float t[32][33];
  int b = blockIdx.z, c0 = blockIdx.y * 32, n0 = blockIdx.x * 32;
  int tx = threadIdx.x, ty = threadIdx.y;
  t[ty][tx] = x[((size_t)b * CC + c0 + ty) * NN + n0 + tx];
  __syncthreads();
  float v = t[tx][ty];
  size_t o = ((size_t)b * NN + n0 + ty) * CC + c0 + tx;
  __nv_bfloat16 h = __float2bfloat16_rn(v);
  d_XTh[o] = h;
  d_XTl[o] = __float2bfloat16_rn(v - __bfloat162float(h));
}

// ---------------------------------------------------------------------------
// conv_fused: grid (32 n, 3, 8 b)
// y=0: theta = x^T @ tw^T -> hi/lo bf16 [n][ci]
// y=1: phi   = x^T @ pw^T -> fp32 [n][ci]
// y=2: g     = gw @ x     -> fp32 [c][n]
// ---------------------------------------------------------------------------
__global__ __launch_bounds__(256) void conv_fused_kernel() {
  MMA_PROLOGUE
  const int b = blockIdx.z, n0 = blockIdx.x * 128, role = blockIdx.y;
  if (role < 2) {
    const int w0 = role * 128;
    mma_pipeline<4>(d_XTh + ((size_t)b * NN + n0) * CC, d_XTl + ((size_t)b * NN + n0) * CC,
                    d_TPWh + (size_t)w0 * CC, d_TPWl + (size_t)w0 * CC,
                    CC, CC, sb, tid, wm, wn, lane, C);
    const int nbase = n0 + wm * 32 + (lane >> 2);
    const int wbase = wn * 64 + (lane & 3) * 2;
#pragma unroll
    for (int mi = 0; mi < 2; mi++)
#pragma unroll
      for (int nj = 0; nj < 8; nj++) {
        int n = nbase + mi * 16;
        int w = wbase + nj * 8;
        float b0v = d_bcat[w0 + w], b1v = d_bcat[w0 + w + 1];
        float v00 = C[mi][nj][0] + b0v, v01 = C[mi][nj][1] + b1v;
        float v10 = C[mi][nj][2] + b0v, v11 = C[mi][nj][3] + b1v;
        if (role == 0) {
          __nv_bfloat162 h, l;
          split2(v00, v01, h, l);
          *(__nv_bfloat162*)&d_Th[((size_t)b * NN + n) * CI + w] = h;
          *(__nv_bfloat162*)&d_Tl[((size_t)b * NN + n) * CI + w] = l;
          split2(v10, v11, h, l);
          *(__nv_bfloat162*)&d_Th[((size_t)b * NN + n + 8) * CI + w] = h;
          *(__nv_bfloat162*)&d_Tl[((size_t)b * NN + n + 8) * CI + w] = l;
        } else {
          *(float2*)&d_PHI[((size_t)b * NN + n) * CI + w] = make_float2(v00, v01);
          *(float2*)&d_PHI[((size_t)b * NN + n + 8) * CI + w] = make_float2(v10, v11);
        }
      }
  } else {
    mma_pipeline<4>(d_GWh, d_GWl,
                    d_XTh + ((size_t)b * NN + n0) * CC, d_XTl + ((size_t)b * NN + n0) * CC,
                    CC, CC, sb, tid, wm, wn, lane, C);
    const int cbase = wm * 32 + (lane >> 2);
    const int nbase = n0 + wn * 64 + (lane & 3) * 2;
#pragma unroll
    for (int mi = 0; mi < 2; mi++)
#pragma unroll
      for (int nj = 0; nj < 8; nj++) {
        int c = cbase + mi * 16;
        int n = nbase + nj * 8;
        float g0 = d_bcat[256 + c], g8 = d_bcat[256 + c + 8];
        *(float2*)&d_G[((size_t)b * CI + c) * NN + n] =
            make_float2(C[mi][nj][0] + g0, C[mi][nj][1] + g0);
        *(float2*)&d_G[((size_t)b * CI + c + 8) * NN + n] =
            make_float2(C[mi][nj][2] + g8, C[mi][nj][3] + g8);
      }
  }
}

// ---------------------------------------------------------------------------
// pool: phi [n][ci] -> [m][ci] hi/lo; g [c][n] -> [c][m] hi/lo (merged)
// ---------------------------------------------------------------------------
__global__ __launch_bounds__(256) void pool_kernel() {
  int gidx = blockIdx.x * 256 + threadIdx.x;
  const int HALF = BB * MM * CI;
  if (gidx < HALF) {
    int idx = gidx;
    int c = idx & 127;
    int m = (idx >> 7) & 1023;
    int b = idx >> 17;
    int n1 = (m >> 5) * 128 + (m & 31) * 2;
    const float* p = d_PHI + ((size_t)b * NN + n1) * CI + c;
    float v = fmaxf(fmaxf(p[0], p[CI]), fmaxf(p[64 * CI], p[65 * CI]));
    __nv_bfloat16 h = __float2bfloat16_rn(v);
    size_t o = ((size_t)b * MM + m) * CI + c;
    d_PHh[o] = h;
    d_PHl[o] = __float2bfloat16_rn(v - __bfloat162float(h));
  } else {
    int idx = gidx - HALF;
    int m = idx & 1023;
    int c = (idx >> 10) & 127;
    int b = idx >> 17;
    int n1 = (m >> 5) * 128 + (m & 31) * 2;
    const float* p = d_G + ((size_t)b * CI + c) * NN + n1;
    float v = fmaxf(fmaxf(p[0], p[1]), fmaxf(p[64], p[65]));
    __nv_bfloat16 h = __float2bfloat16_rn(v);
    size_t o = ((size_t)b * CI + c) * MM + m;
    d_Gh[o] = h;
    d_Gl[o] = __float2bfloat16_rn(v - __bfloat162float(h));
  }
}

// ---------------------------------------------------------------------------
// s_mma: S[b][q][m] = theta phi^T. A=theta (rows q), B=phi (rows m). grid (8,32,8)
// ---------------------------------------------------------------------------
__global__ __launch_bounds__(256) void s_mma_kernel() {
  MMA_PROLOGUE
  const int b = blockIdx.z, q0 = blockIdx.y * 128, m0 = blockIdx.x * 128;
  mma_pipeline<2>(d_Th + ((size_t)b * NN + q0) * CI, d_Tl + ((size_t)b * NN + q0) * CI,
                  d_PHh + ((size_t)b * MM + m0) * CI, d_PHl + ((size_t)b * MM + m0) * CI,
                  CI, CI, sb, tid, wm, wn, lane, C);
  float* Sb = d_S + (size_t)b * NN * MM;
  const int qbase = q0 + wm * 32 + (lane >> 2);
  const int mbase = m0 + wn * 64 + (lane & 3) * 2;
#pragma unroll
  for (int mi = 0; mi < 2; mi++)
#pragma unroll
    for (int nj = 0; nj < 8; nj++) {
      int q = qbase + mi * 16;
      int m = mbase + nj * 8;
      *(float2*)&Sb[(size_t)q * MM + m] = make_float2(C[mi][nj][0], C[mi][nj][1]);
      *(float2*)&Sb[(size_t)(q + 8) * MM + m] = make_float2(C[mi][nj][2], C[mi][nj][3]);
    }
}

// ---------------------------------------------------------------------------
// softmax over M=1024, writes hi/lo bf16 probabilities
// ---------------------------------------------------------------------------
__global__ __launch_bounds__(128) void softmax_kernel() {
  const float* row = d_S + (size_t)blockIdx.x * MM;
  const int t = threadIdx.x;
  float4 v0 = *(const float4*)&row[t * 8];
  float4 v1 = *(const float4*)&row[t * 8 + 4];
  float mx = fmaxf(fmaxf(fmaxf(v0.x, v0.y), fmaxf(v0.z, v0.w)),
                   fmaxf(fmaxf(v1.x, v1.y), fmaxf(v1.z, v1.w)));
  __shared__ float red[4];
#pragma unroll
  for (int o = 16; o; o >>= 1) mx = fmaxf(mx, __shfl_xor_sync(0xffffffffu, mx, o));
  if ((t & 31) == 0) red[t >> 5] = mx;
  __syncthreads();
  mx = fmaxf(fmaxf(red[0], red[1]), fmaxf(red[2], red[3]));
  v0.x = __expf(v0.x - mx); v0.y = __expf(v0.y - mx);
  v0.z = __expf(v0.z - mx); v0.w = __expf(v0.w - mx);
  v1.x = __expf(v1.x - mx); v1.y = __expf(v1.y - mx);
  v1.z = __expf(v1.z - mx); v1.w = __expf(v1.w - mx);
  float s = v0.x + v0.y + v0.z + v0.w + v1.x + v1.y + v1.z + v1.w;
  __syncthreads();
#pragma unroll
  for (int o = 16; o; o >>= 1) s += __shfl_xor_sync(0xffffffffu, s, o);
  if ((t & 31) == 0) red[t >> 5] = s;
  __syncthreads();
  float inv = 1.0f / (red[0] + red[1] + red[2] + red[3]);
  float p[8] = {v0.x * inv, v0.y * inv, v0.z * inv, v0.w * inv,
                v1.x * inv, v1.y * inv, v1.z * inv, v1.w * inv};
  size_t base = (size_t)blockIdx.x * MM + t * 8;
  __nv_bfloat16 hbuf[8], lbuf[8];
#pragma unroll
  for (int j = 0; j < 8; j++) {
    __nv_bfloat16 h = __float2bfloat16_rn(p[j]);
    hbuf[j] = h;
    lbuf[j] = __float2bfloat16_rn(p[j] - __bfloat162float(h));
  }
  *(uint4*)&d_Ph[base] = *(uint4*)hbuf;
  *(uint4*)&d_Pl[base] = *(uint4*)lbuf;
}

// ---------------------------------------------------------------------------
// y_mma: Y[q][c] = P @ g^T. A=P (rows q), B=g (rows c, K=m). grid (32,1,8)
// ---------------------------------------------------------------------------
__global__ __launch_bounds__(256) void y_mma_kernel() {
  MMA_PROLOGUE
  const int b = blockIdx.z, q0 = blockIdx.x * 128;
  mma_pipeline<16>(d_Ph + ((size_t)b * NN + q0) * MM, d_Pl + ((size_t)b * NN + q0) * MM,
                   d_Gh + (size_t)b * CI * MM, d_Gl + (size_t)b * CI * MM,
                   MM, MM, sb, tid, wm, wn, lane, C);
  const int qbase = q0 + wm * 32 + (lane >> 2);
  const int cbase = wn * 64 + (lane & 3) * 2;
#pragma unroll
  for (int mi = 0; mi < 2; mi++)
#pragma unroll
    for (int nj = 0; nj < 8; nj++) {
      int q = qbase + mi * 16;
      int c = cbase + nj * 8;
      __nv_bfloat162 h, l;
      split2(C[mi][nj][0], C[mi][nj][1], h, l);
      *(__nv_bfloat162*)&d_Yh[((size_t)b * NN + q) * CI + c] = h;
      *(__nv_bfloat162*)&d_Yl[((size_t)b * NN + q) * CI + c] = l;
      split2(C[mi][nj][2], C[mi][nj][3], h, l);
      *(__nv_bfloat162*)&d_Yh[((size_t)b * NN + q + 8) * CI + c] = h;
      *(__nv_bfloat162*)&d_Yl[((size_t)b * NN + q + 8) * CI + c] = l;
    }
}

// ---------------------------------------------------------------------------
// wconv: WY[o][n] = W_w @ Y^T + W_b, + BN stats. grid (32 n, 2 o, 8 b)
// ---------------------------------------------------------------------------
__global__ __launch_bounds__(256) void wconv_mma_kernel(const float* __restrict__ Wb) {
  MMA_PROLOGUE
  __shared__ float s_sum[128];
  __shared__ float s_sq[128];
  const int b = blockIdx.z, n0 = blockIdx.x * 128, o0 = blockIdx.y * 128;
  if (tid < 128) { s_sum[tid] = 0.f; s_sq[tid] = 0.f; }
  mma_pipeline<2>(d_WWh + (size_t)o0 * CI, d_WWl + (size_t)o0 * CI,
                  d_Yh + ((size_t)b * NN + n0) * CI, d_Yl + ((size_t)b * NN + n0) * CI,
                  CI, CI, sb, tid, wm, wn, lane, C);
  const int orow0 = wm * 32 + (lane >> 2);
  const int nbase = n0 + wn * 64 + (lane & 3) * 2;
  float ls[2][2] = {}, lq[2][2] = {};
  float* WYb = d_WY + (size_t)b * CC * NN;
#pragma unroll
  for (int mi = 0; mi < 2; mi++) {
    int o = o0 + orow0 + mi * 16;
    float bias0 = Wb[o], bias8 = Wb[o + 8];
#pragma unroll
    for (int nj = 0; nj < 8; nj++) {
      int n = nbase + nj * 8;
      float v0 = C[mi][nj][0] + bias0, v1 = C[mi][nj][1] + bias0;
      float v2 = C[mi][nj][2] + bias8, v3 = C[mi][nj][3] + bias8;
      ls[mi][0] += v0 + v1;
      lq[mi][0] += v0 * v0 + v1 * v1;
      ls[mi][1] += v2 + v3;
      lq[mi][1] += v2 * v2 + v3 * v3;
      *(float2*)&WYb[(size_t)o * NN + n] = make_float2(v0, v1);
      *(float2*)&WYb[(size_t)(o + 8) * NN + n] = make_float2(v2, v3);
    }
  }
#pragma unroll
  for (int mi = 0; mi < 2; mi++)
#pragma unroll
    for (int h = 0; h < 2; h++) {
      int orow = orow0 + mi * 16 + h * 8;
      atomicAdd(&s_sum[orow], ls[mi][h]);
      atomicAdd(&s_sq[orow], lq[mi][h]);
    }
  __syncthreads();
  if (tid < 128) {
    atomicAdd(&d_sum[o0 + tid], (double)s_sum[tid]);
    atomicAdd(&d_sq[o0 + tid], (double)s_sq[tid]);
  }
}

// ---------------------------------------------------------------------------
// BN finalize
// ---------------------------------------------------------------------------
__global__ void bnprep_kernel(const float* __restrict__ gamma,
                              const float* __restrict__ beta) {
  int o = threadIdx.x;
  double cnt = (double)BB * (double)NN;
  double mean = d_sum[o] / cnt;
  double var = d_sq[o] / cnt - mean * mean;
  float sc = gamma[o] * rsqrtf((float)var + BN_EPS);
  d_scale[o] = sc;
  d_shift[o] = beta[o] - (float)mean * sc;
}

// ---------------------------------------------------------------------------
// final: out = WY*scale + shift + x
// ---------------------------------------------------------------------------
__global__ __launch_bounds__(256) void final_kernel(const float* __restrict__ x,
                                                    float* __restrict__ out) {
  size_t i4 = (size_t)blockIdx.x * 256 + threadIdx.x;
  int o = (int)((i4 >> 10) & 255);
  float sc = d_scale[o], sh = d_shift[o];
  float4 w = ((const float4*)d_WY)[i4];
  float4 xi = ((const float4*)x)[i4];
  float4 r;
  r.x = w.x * sc + sh + xi.x;
  r.y = w.y * sc + sh + xi.y;
  r.z = w.z * sc + sh + xi.z;
  r.w = w.w * sc + sh + xi.w;
  ((float4*)out)[i4] = r;
}

// ---------------------------------------------------------------------------
// launch
// ---------------------------------------------------------------------------
extern "C" void kernel_launch(void* const* d_in, const int* in_sizes, int n_in,
                              void* d_out, int out_size) {
  const float* x  = (const float*)d_in[0];
  const float* tw = (const float*)d_in[1];
  const float* tb = (const float*)d_in[2];
  const float* pw = (const float*)d_in[3];
  const float* pb = (const float*)d_in[4];
  const float* gw = (const float*)d_in[5];
  const float* gb = (const float*)d_in[6];
  const float* Ww = (const float*)d_in[7];
  const float* Wb = (const float*)d_in[8];
  const float* bg = (const float*)d_in[9];
  const float* bb = (const float*)d_in[10];
  float* out = (float*)d_out;

  cudaFuncSetAttribute(conv_fused_kernel, cudaFuncAttributeMaxDynamicSharedMemorySize, DSMEM_BYTES);
  cudaFuncSetAttribute(s_mma_kernel, cudaFuncAttributeMaxDynamicSharedMemorySize, DSMEM_BYTES);
  cudaFuncSetAttribute(y_mma_kernel, cudaFuncAttributeMaxDynamicSharedMemorySize, DSMEM_BYTES);
  cudaFuncSetAttribute(wconv_mma_kernel, cudaFuncAttributeMaxDynamicSharedMemorySize, DSMEM_BYTES);

  init_kernel<<<512, 256>>>(tw, tb, pw, pb, gw, gb, Ww);
  xsplit_kernel<<<dim3(128, 8, BB), dim3(32, 32)>>>(x);
  conv_fused_kernel<<<dim3(32, 3, BB), 256, DSMEM_BYTES>>>();
  pool_kernel<<<(2 * BB * MM * CI) / 256, 256>>>();
  s_mma_kernel<<<dim3(8, 32, BB), 256, DSMEM_BYTES>>>();
  softmax_kernel<<<BB * NN, 128>>>();
  y_mma_kernel<<<dim3(32, 1, BB), 256, DSMEM_BYTES>>>();
  wconv_mma_kernel<<<dim3(32, 2, BB), 256, DSMEM_BYTES>>>(Wb);
  bnprep_kernel<<<1, 256>>>(bg, bb);
  final_kernel<<<(BB * CC * NN / 4) / 256, 256>>>(x, out);
}

// round 11
// speedup vs baseline: 1.7484x; 1.1840x over previous
#include <cuda_runtime.h>
#include <cuda_bf16.h>
#include <cstdint>

// Problem constants
#define BB 8
#define CC 256
#define CI 128
#define NN 4096          // H*W
#define MM 1024          // (H/2)*(W/2)
#define BN_EPS 1e-5f

// ---------------------------------------------------------------------------
// Scratch (static __device__ allocations only)
// ---------------------------------------------------------------------------
__device__ float d_PHI[(size_t)BB * NN * CI];     // phi full-res [n][ci] fp32
__device__ float d_G[(size_t)BB * CI * NN];       // g full-res [c][n] fp32
__device__ float d_WY[(size_t)BB * CC * NN];      // W conv output (pre-BN) [o][n]
__device__ float d_bcat[384];                     // theta|phi|g biases
__device__ double d_sum[CC];
__device__ double d_sq[CC];
__device__ float d_scale[CC];
__device__ float d_shift[CC];
// hi/lo bf16 split operands
__device__ __nv_bfloat16 d_XTh[(size_t)BB * NN * CC];  // x^T [b][n][c]
__device__ __nv_bfloat16 d_XTl[(size_t)BB * NN * CC];
__device__ __nv_bfloat16 d_TPWh[256 * CC];             // theta(0:128)|phi(128:256) weights
__device__ __nv_bfloat16 d_TPWl[256 * CC];
__device__ __nv_bfloat16 d_GWh[CI * CC];               // g weights
__device__ __nv_bfloat16 d_GWl[CI * CC];
__device__ __nv_bfloat16 d_WWh[CC * CI];               // W weights
__device__ __nv_bfloat16 d_WWl[CC * CI];
__device__ __nv_bfloat16 d_Th[(size_t)BB * NN * CI];   // theta [b][n][ci]
__device__ __nv_bfloat16 d_Tl[(size_t)BB * NN * CI];
__device__ __nv_bfloat16 d_PHh[(size_t)BB * MM * CI];  // pooled phi [b][m][ci]
__device__ __nv_bfloat16 d_PHl[(size_t)BB * MM * CI];
__device__ __nv_bfloat16 d_Gh[(size_t)BB * CI * MM];   // pooled g [b][c][m]
__device__ __nv_bfloat16 d_Gl[(size_t)BB * CI * MM];
__device__ __nv_bfloat16 d_Yh[(size_t)BB * NN * CI];   // attention out [b][n][ci]
__device__ __nv_bfloat16 d_Yl[(size_t)BB * NN * CI];

// ---------------------------------------------------------------------------
// mma.sync + cp.async helpers
// ---------------------------------------------------------------------------
__device__ __forceinline__ uint32_t smem_u32(const void* p) {
  uint32_t a;
  asm("{ .reg .u64 t; cvta.to.shared.u64 t, %1; cvt.u32.u64 %0, t; }" : "=r"(a) : "l"(p));
  return a;
}
__device__ __forceinline__ void ldm_x4(uint32_t* r, uint32_t addr) {
  asm volatile("ldmatrix.sync.aligned.m8n8.x4.shared.b16 {%0,%1,%2,%3}, [%4];"
               : "=r"(r[0]), "=r"(r[1]), "=r"(r[2]), "=r"(r[3]) : "r"(addr));
}
__device__ __forceinline__ void mma_bf16(float* c, const uint32_t* a, uint32_t b0, uint32_t b1) {
  asm volatile(
      "mma.sync.aligned.m16n8k16.row.col.f32.bf16.bf16.f32 "
      "{%0,%1,%2,%3}, {%4,%5,%6,%7}, {%8,%9}, {%0,%1,%2,%3};"
      : "+f"(c[0]), "+f"(c[1]), "+f"(c[2]), "+f"(c[3])
      : "r"(a[0]), "r"(a[1]), "r"(a[2]), "r"(a[3]), "r"(b0), "r"(b1));
}
__device__ __forceinline__ void cpa16(uint32_t dst, const void* src) {
  asm volatile("cp.async.cg.shared.global [%0], [%1], 16;" :: "r"(dst), "l"(src));
}
__device__ __forceinline__ void split2(float a, float b, __nv_bfloat162& h, __nv_bfloat162& l) {
  __nv_bfloat16 h0 = __float2bfloat16_rn(a), h1 = __float2bfloat16_rn(b);
  __nv_bfloat16 l0 = __float2bfloat16_rn(a - __bfloat162float(h0));
  __nv_bfloat16 l1 = __float2bfloat16_rn(b - __bfloat162float(h1));
  h = __halves2bfloat162(h0, h1);
  l = __halves2bfloat162(l0, l1);
}

// smem tile: 128 rows x 64 bf16, padded row stride 72 elems (272B)
#define TPAD 72
#define TILE_ELEMS (128 * TPAD)
#define TILE_BYTES (TILE_ELEMS * 2)        // 18432
#define STAGE_BYTES (4 * TILE_BYTES)
#define DSMEM_BYTES (2 * STAGE_BYTES)      // 147456 (generic GEMMs)
#define ATTN_SMEM (12 * TILE_BYTES + 768 * 4)  // 224256 (attn kernel)

__device__ __forceinline__ void load_tile_async(uint32_t sbase, const __nv_bfloat16* g,
                                                int gstride, int tid) {
#pragma unroll
  for (int i = 0; i < 4; i++) {
    int idx = tid + i * 256;
    int row = idx >> 3, c4 = idx & 7;
    cpa16(sbase + (uint32_t)(row * TPAD + c4 * 8) * 2,
          g + (size_t)row * gstride + c4 * 8);
  }
}

// Warp-level 128x128 GEMM over one 64-wide k-chunk in smem. Hi/lo split: 3 terms.
__device__ __forceinline__ void chunk_mma(uint32_t sAh, uint32_t sAl, uint32_t sBh,
                                          uint32_t sBl, int wm, int wn, int lane,
                                          float (&C)[2][8][4]) {
  const int ar = wm * 32 + (lane & 15);
  const int ac = (lane >> 4) * 8;
  const int bg = lane >> 3;
  const int br = wn * 64 + ((bg & 2) << 2) + (lane & 7);
  const int bc = (bg & 1) << 3;
#pragma unroll
  for (int kk = 0; kk < 4; kk++) {
    uint32_t Ah[2][4], Al[2][4], Bh[4][4], Bl[4][4];
    uint32_t aoff = ((ar) * TPAD + kk * 16 + ac) * 2;
    ldm_x4(Ah[0], sAh + aoff);
    ldm_x4(Ah[1], sAh + aoff + 16 * TPAD * 2);
    ldm_x4(Al[0], sAl + aoff);
    ldm_x4(Al[1], sAl + aoff + 16 * TPAD * 2);
#pragma unroll
    for (int p = 0; p < 4; p++) {
      uint32_t boff = ((br + p * 16) * TPAD + kk * 16 + bc) * 2;
      ldm_x4(Bh[p], sBh + boff);
      ldm_x4(Bl[p], sBl + boff);
    }
#pragma unroll
    for (int mi = 0; mi < 2; mi++)
#pragma unroll
      for (int p = 0; p < 4; p++)
#pragma unroll
        for (int h = 0; h < 2; h++) {
          float* acc = C[mi][p * 2 + h];
          mma_bf16(acc, Ah[mi], Bh[p][h * 2], Bh[p][h * 2 + 1]);
          mma_bf16(acc, Ah[mi], Bl[p][h * 2], Bl[p][h * 2 + 1]);
          mma_bf16(acc, Al[mi], Bh[p][h * 2], Bh[p][h * 2 + 1]);
        }
  }
}

// Double-buffered cp.async pipeline over NCH 64-wide k-chunks.
template <int NCH>
__device__ __forceinline__ void mma_pipeline(const __nv_bfloat16* gAh, const __nv_bfloat16* gAl,
                                             const __nv_bfloat16* gBh, const __nv_bfloat16* gBl,
                                             int sA, int sB, uint32_t sb, int tid,
                                             int wm, int wn, int lane, float (&C)[2][8][4]) {
  {
    load_tile_async(sb, gAh, sA, tid);
    load_tile_async(sb + TILE_BYTES, gAl, sA, tid);
    load_tile_async(sb + 2 * TILE_BYTES, gBh, sB, tid);
    load_tile_async(sb + 3 * TILE_BYTES, gBl, sB, tid);
    asm volatile("cp.async.commit_group;");
  }
#pragma unroll 1
  for (int ch = 0; ch < NCH; ch++) {
    if (ch + 1 < NCH) {
      uint32_t nb = sb + ((ch + 1) & 1) * STAGE_BYTES;
      int ko = (ch + 1) * 64;
      load_tile_async(nb, gAh + ko, sA, tid);
      load_tile_async(nb + TILE_BYTES, gAl + ko, sA, tid);
      load_tile_async(nb + 2 * TILE_BYTES, gBh + ko, sB, tid);
      load_tile_async(nb + 3 * TILE_BYTES, gBl + ko, sB, tid);
      asm volatile("cp.async.commit_group;");
      asm volatile("cp.async.wait_group 1;");
    } else {
      asm volatile("cp.async.wait_group 0;");
    }
    __syncthreads();
    uint32_t cb = sb + (ch & 1) * STAGE_BYTES;
    chunk_mma(cb, cb + TILE_BYTES, cb + 2 * TILE_BYTES, cb + 3 * TILE_BYTES, wm, wn, lane, C);
    __syncthreads();
  }
}

#define MMA_PROLOGUE                                              \
  extern __shared__ __align__(16) __nv_bfloat16 dsm[];            \
  const uint32_t sb = smem_u32(dsm);                              \
  const int tid = threadIdx.x, wid = tid >> 5, lane = tid & 31;   \
  const int wm = wid >> 1, wn = wid & 1;                          \
  float C[2][8][4] = {};

// ---------------------------------------------------------------------------
// init: split all weights to hi/lo bf16, pack biases, zero BN accumulators
// ---------------------------------------------------------------------------
__global__ __launch_bounds__(256) void init_kernel(
    const float* __restrict__ tw, const float* __restrict__ tb,
    const float* __restrict__ pw, const float* __restrict__ pb,
    const float* __restrict__ gw, const float* __restrict__ gb,
    const float* __restrict__ Ww) {
  int idx = blockIdx.x * 256 + threadIdx.x;
  if (idx < CC) { d_sum[idx] = 0.0; d_sq[idx] = 0.0; }
  if (idx < 384)
    d_bcat[idx] = (idx < 128) ? tb[idx] : (idx < 256) ? pb[idx - 128] : gb[idx - 256];
  float v;
  __nv_bfloat16 h;
  if (idx < 65536) {  // theta|phi weights [256][256]
    v = (idx < 32768) ? tw[idx] : pw[idx - 32768];
    h = __float2bfloat16_rn(v);
    d_TPWh[idx] = h;
    d_TPWl[idx] = __float2bfloat16_rn(v - __bfloat162float(h));
  } else if (idx < 98304) {  // g weights [128][256]
    int j = idx - 65536;
    v = gw[j];
    h = __float2bfloat16_rn(v);
    d_GWh[j] = h;
    d_GWl[j] = __float2bfloat16_rn(v - __bfloat162float(h));
  } else if (idx < 131072) {  // W weights [256][128]
    int j = idx - 98304;
    v = Ww[j];
    h = __float2bfloat16_rn(v);
    d_WWh[j] = h;
    d_WWl[j] = __float2bfloat16_rn(v - __bfloat162float(h));
  }
}

// ---------------------------------------------------------------------------
// xsplit: transpose x [c][n] -> x^T hi/lo bf16 [n][c]
// ---------------------------------------------------------------------------
__global__ void xsplit_kernel(const float* __restrict__ x) {  // (32,32), grid (128,8,8)
  __shared__ float t[32][33];
  int b = blockIdx.z, c0 = blockIdx.y * 32, n0 = blockIdx.x * 32;
  int tx = threadIdx.x, ty = threadIdx.y;
  t[ty][tx] = x[((size_t)b * CC + c0 + ty) * NN + n0 + tx];
  __syncthreads();
  float v = t[tx][ty];
  size_t o = ((size_t)b * NN + n0 + ty) * CC + c0 + tx;
  __nv_bfloat16 h = __float2bfloat16_rn(v);
  d_XTh[o] = h;
  d_XTl[o] = __float2bfloat16_rn(v - __bfloat162float(h));
}

// ---------------------------------------------------------------------------
// conv_fused: grid (32 n, 3, 8 b)
// ---------------------------------------------------------------------------
__global__ __launch_bounds__(256) void conv_fused_kernel() {
  MMA_PROLOGUE
  const int b = blockIdx.z, n0 = blockIdx.x * 128, role = blockIdx.y;
  if (role < 2) {
    const int w0 = role * 128;
    mma_pipeline<4>(d_XTh + ((size_t)b * NN + n0) * CC, d_XTl + ((size_t)b * NN + n0) * CC,
                    d_TPWh + (size_t)w0 * CC, d_TPWl + (size_t)w0 * CC,
                    CC, CC, sb, tid, wm, wn, lane, C);
    const int nbase = n0 + wm * 32 + (lane >> 2);
    const int wbase = wn * 64 + (lane & 3) * 2;
#pragma unroll
    for (int mi = 0; mi < 2; mi++)
#pragma unroll
      for (int nj = 0; nj < 8; nj++) {
        int n = nbase + mi * 16;
        int w = wbase + nj * 8;
        float b0v = d_bcat[w0 + w], b1v = d_bcat[w0 + w + 1];
        float v00 = C[mi][nj][0] + b0v, v01 = C[mi][nj][1] + b1v;
        float v10 = C[mi][nj][2] + b0v, v11 = C[mi][nj][3] + b1v;
        if (role == 0) {
          __nv_bfloat162 h, l;
          split2(v00, v01, h, l);
          *(__nv_bfloat162*)&d_Th[((size_t)b * NN + n) * CI + w] = h;
          *(__nv_bfloat162*)&d_Tl[((size_t)b * NN + n) * CI + w] = l;
          split2(v10, v11, h, l);
          *(__nv_bfloat162*)&d_Th[((size_t)b * NN + n + 8) * CI + w] = h;
          *(__nv_bfloat162*)&d_Tl[((size_t)b * NN + n + 8) * CI + w] = l;
        } else {
          *(float2*)&d_PHI[((size_t)b * NN + n) * CI + w] = make_float2(v00, v01);
          *(float2*)&d_PHI[((size_t)b * NN + n + 8) * CI + w] = make_float2(v10, v11);
        }
      }
  } else {
    mma_pipeline<4>(d_GWh, d_GWl,
                    d_XTh + ((size_t)b * NN + n0) * CC, d_XTl + ((size_t)b * NN + n0) * CC,
                    CC, CC, sb, tid, wm, wn, lane, C);
    const int cbase = wm * 32 + (lane >> 2);
    const int nbase = n0 + wn * 64 + (lane & 3) * 2;
#pragma unroll
    for (int mi = 0; mi < 2; mi++)
#pragma unroll
      for (int nj = 0; nj < 8; nj++) {
        int c = cbase + mi * 16;
        int n = nbase + nj * 8;
        float g0 = d_bcat[256 + c], g8 = d_bcat[256 + c + 8];
        *(float2*)&d_G[((size_t)b * CI + c) * NN + n] =
            make_float2(C[mi][nj][0] + g0, C[mi][nj][1] + g0);
        *(float2*)&d_G[((size_t)b * CI + c + 8) * NN + n] =
            make_float2(C[mi][nj][2] + g8, C[mi][nj][3] + g8);
      }
  }
}

// ---------------------------------------------------------------------------
// pool: phi [n][ci] -> [m][ci] hi/lo; g [c][n] -> [c][m] hi/lo (merged)
// ---------------------------------------------------------------------------
__global__ __launch_bounds__(256) void pool_kernel() {
  int gidx = blockIdx.x * 256 + threadIdx.x;
  const int HALF = BB * MM * CI;
  if (gidx < HALF) {
    int idx = gidx;
    int c = idx & 127;
    int m = (idx >> 7) & 1023;
    int b = idx >> 17;
    int n1 = (m >> 5) * 128 + (m & 31) * 2;
    const float* p = d_PHI + ((size_t)b * NN + n1) * CI + c;
    float v = fmaxf(fmaxf(p[0], p[CI]), fmaxf(p[64 * CI], p[65 * CI]));
    __nv_bfloat16 h = __float2bfloat16_rn(v);
    size_t o = ((size_t)b * MM + m) * CI + c;
    d_PHh[o] = h;
    d_PHl[o] = __float2bfloat16_rn(v - __bfloat162float(h));
  } else {
    int idx = gidx - HALF;
    int m = idx & 1023;
    int c = (idx >> 10) & 127;
    int b = idx >> 17;
    int n1 = (m >> 5) * 128 + (m & 31) * 2;
    const float* p = d_G + ((size_t)b * CI + c) * NN + n1;
    float v = fmaxf(fmaxf(p[0], p[1]), fmaxf(p[64], p[65]));
    __nv_bfloat16 h = __float2bfloat16_rn(v);
    size_t o = ((size_t)b * CI + c) * MM + m;
    d_Gh[o] = h;
    d_Gl[o] = __float2bfloat16_rn(v - __bfloat162float(h));
  }
}

// ---------------------------------------------------------------------------
// attn: fused S = theta phi^T -> online softmax -> Y = P g^T.
// grid (32 q-tiles, 1, 8 b), 256 threads.
// smem: theta[4 tiles, persistent] | phi/P[4 tiles] | g[4 tiles] | stats
// tile slots within a region: {h ksub0, h ksub1, l ksub0, l ksub1}
// ---------------------------------------------------------------------------
__global__ __launch_bounds__(256, 1) void attn_kernel() {
  extern __shared__ __align__(16) char smemc[];
  const uint32_t sb = smem_u32(smemc);
  const int tid = threadIdx.x, wid = tid >> 5, lane = tid & 31;
  const int wm = wid >> 1, wn = wid & 1;
  const int b = blockIdx.z, q0 = blockIdx.x * 128;
  const uint32_t sT = sb;
  const uint32_t sP = sb + 4 * TILE_BYTES;   // phi, then P
  const uint32_t sG = sb + 8 * TILE_BYTES;
  float* run_max = (float*)(smemc + 12 * TILE_BYTES);
  float* run_sum = run_max + 128;
  float* redm = run_sum + 128;   // [256] per-wn chunk max
  float* reds = redm + 256;      // [256] per-wn chunk sum

  if (tid < 128) { run_max[tid] = -1e30f; run_sum[tid] = 0.f; }

  const __nv_bfloat16* Tg_h = d_Th + ((size_t)b * NN + q0) * CI;
  const __nv_bfloat16* Tg_l = d_Tl + ((size_t)b * NN + q0) * CI;
  const __nv_bfloat16* PH_h = d_PHh + (size_t)b * MM * CI;
  const __nv_bfloat16* PH_l = d_PHl + (size_t)b * MM * CI;
  const __nv_bfloat16* G_h = d_Gh + (size_t)b * CI * MM;
  const __nv_bfloat16* G_l = d_Gl + (size_t)b * CI * MM;

  // prologue: theta (persistent) + phi chunk 0  -> group 1
  load_tile_async(sT + 0 * TILE_BYTES, Tg_h, CI, tid);
  load_tile_async(sT + 1 * TILE_BYTES, Tg_h + 64, CI, tid);
  load_tile_async(sT + 2 * TILE_BYTES, Tg_l, CI, tid);
  load_tile_async(sT + 3 * TILE_BYTES, Tg_l + 64, CI, tid);
  load_tile_async(sP + 0 * TILE_BYTES, PH_h, CI, tid);
  load_tile_async(sP + 1 * TILE_BYTES, PH_h + 64, CI, tid);
  load_tile_async(sP + 2 * TILE_BYTES, PH_l, CI, tid);
  load_tile_async(sP + 3 * TILE_BYTES, PH_l + 64, CI, tid);
  asm volatile("cp.async.commit_group;");

  float Cy[2][8][4] = {};
  const int r0base = wm * 32 + (lane >> 2);

#pragma unroll 1
  for (int ch = 0; ch < 8; ch++) {
    const int m0 = ch * 128;
    // issue g(ch) (overlaps S compute)
    load_tile_async(sG + 0 * TILE_BYTES, G_h + m0, MM, tid);
    load_tile_async(sG + 1 * TILE_BYTES, G_h + m0 + 64, MM, tid);
    load_tile_async(sG + 2 * TILE_BYTES, G_l + m0, MM, tid);
    load_tile_async(sG + 3 * TILE_BYTES, G_l + m0 + 64, MM, tid);
    asm volatile("cp.async.commit_group;");
    asm volatile("cp.async.wait_group 1;");   // theta+phi(ch) ready
    __syncthreads();

    // S chunk = theta @ phi(ch)^T  (K = ci = 2 sub-chunks)
    float Cs[2][8][4] = {};
    chunk_mma(sT, sT + 2 * TILE_BYTES, sP, sP + 2 * TILE_BYTES, wm, wn, lane, Cs);
    chunk_mma(sT + TILE_BYTES, sT + 3 * TILE_BYTES, sP + TILE_BYTES, sP + 3 * TILE_BYTES,
              wm, wn, lane, Cs);
    __syncthreads();   // all phi reads done; phi region now reusable for P

    // ---- online softmax ----
    // local row max over this thread's 16 values per (mi, half)
    float nm_[2][2], sc_[2][2];
#pragma unroll
    for (int mi = 0; mi < 2; mi++)
#pragma unroll
      for (int h = 0; h < 2; h++) {
        float lm = -1e30f;
#pragma unroll
        for (int nj = 0; nj < 8; nj++)
          lm = fmaxf(lm, fmaxf(Cs[mi][nj][2 * h], Cs[mi][nj][2 * h + 1]));
        lm = fmaxf(lm, __shfl_xor_sync(0xffffffffu, lm, 1));
        lm = fmaxf(lm, __shfl_xor_sync(0xffffffffu, lm, 2));
        if ((lane & 3) == 0) redm[wn * 128 + r0base + mi * 16 + h * 8] = lm;
      }
    __syncthreads();
#pragma unroll
    for (int mi = 0; mi < 2; mi++)
#pragma unroll
      for (int h = 0; h < 2; h++) {
        int r = r0base + mi * 16 + h * 8;
        float cm = fmaxf(redm[r], redm[128 + r]);
        float om = run_max[r];
        float nm = fmaxf(om, cm);
        nm_[mi][h] = nm;
        sc_[mi][h] = __expf(om - nm);
      }
    // exp, P write to smem (hi/lo), local sums
#pragma unroll
    for (int mi = 0; mi < 2; mi++)
#pragma unroll
      for (int h = 0; h < 2; h++) {
        int r = r0base + mi * 16 + h * 8;
        float nm = nm_[mi][h];
        float ls = 0.f;
#pragma unroll
        for (int nj = 0; nj < 8; nj++) {
          float p0 = __expf(Cs[mi][nj][2 * h] - nm);
          float p1 = __expf(Cs[mi][nj][2 * h + 1] - nm);
          ls += p0 + p1;
          __nv_bfloat162 hh, ll;
          split2(p0, p1, hh, ll);
          uint32_t co = (uint32_t)(r * TPAD + nj * 8 + (lane & 3) * 2) * 2;
          *(__nv_bfloat162*)(smemc + (sP - sb) + wn * TILE_BYTES + co) = hh;
          *(__nv_bfloat162*)(smemc + (sP - sb) + (2 + wn) * TILE_BYTES + co) = ll;
        }
        ls += __shfl_xor_sync(0xffffffffu, ls, 1);
        ls += __shfl_xor_sync(0xffffffffu, ls, 2);
        if ((lane & 3) == 0) reds[wn * 128 + r] = ls;
      }
    // rescale Y accumulator
#pragma unroll
    for (int mi = 0; mi < 2; mi++)
#pragma unroll
      for (int nj = 0; nj < 8; nj++) {
        Cy[mi][nj][0] *= sc_[mi][0];
        Cy[mi][nj][1] *= sc_[mi][0];
        Cy[mi][nj][2] *= sc_[mi][1];
        Cy[mi][nj][3] *= sc_[mi][1];
      }
    __syncthreads();   // P + reds visible
    // update running stats (one owner per row)
    if (wn == 0 && (lane & 3) == 0) {
#pragma unroll
      for (int mi = 0; mi < 2; mi++)
#pragma unroll
        for (int h = 0; h < 2; h++) {
          int r = r0base + mi * 16 + h * 8;
          run_sum[r] = run_sum[r] * sc_[mi][h] + reds[r] + reds[128 + r];
          run_max[r] = nm_[mi][h];
        }
    }
    asm volatile("cp.async.wait_group 0;");  // g(ch) ready
    __syncthreads();

    // Y += P @ g(ch)^T  (K = m chunk = 2 sub-chunks)
    chunk_mma(sP, sP + 2 * TILE_BYTES, sG, sG + 2 * TILE_BYTES, wm, wn, lane, Cy);
    chunk_mma(sP + TILE_BYTES, sP + 3 * TILE_BYTES, sG + TILE_BYTES, sG + 3 * TILE_BYTES,
              wm, wn, lane, Cy);
    __syncthreads();   // P/g consumed; safe to refill

    if (ch + 1 < 8) {  // issue phi(ch+1) into P region
      const int mn = (ch + 1) * 128;
      load_tile_async(sP + 0 * TILE_BYTES, PH_h + (size_t)mn * CI, CI, tid);
      load_tile_async(sP + 1 * TILE_BYTES, PH_h + (size_t)mn * CI + 64, CI, tid);
      load_tile_async(sP + 2 * TILE_BYTES, PH_l + (size_t)mn * CI, CI, tid);
      load_tile_async(sP + 3 * TILE_BYTES, PH_l + (size_t)mn * CI + 64, CI, tid);
      asm volatile("cp.async.commit_group;");
    }
  }

  // epilogue: normalize by run_sum, split, store Y [n][ci]
  const int qbase = q0 + wm * 32 + (lane >> 2);
  const int cbase = wn * 64 + (lane & 3) * 2;
#pragma unroll
  for (int mi = 0; mi < 2; mi++) {
    float i0 = 1.0f / run_sum[r0base + mi * 16];
    float i8 = 1.0f / run_sum[r0base + mi * 16 + 8];
#pragma unroll
    for (int nj = 0; nj < 8; nj++) {
      int q = qbase + mi * 16;
      int c = cbase + nj * 8;
      __nv_bfloat162 h, l;
      split2(Cy[mi][nj][0] * i0, Cy[mi][nj][1] * i0, h, l);
      *(__nv_bfloat162*)&d_Yh[((size_t)b * NN + q) * CI + c] = h;
      *(__nv_bfloat162*)&d_Yl[((size_t)b * NN + q) * CI + c] = l;
      split2(Cy[mi][nj][2] * i8, Cy[mi][nj][3] * i8, h, l);
      *(__nv_bfloat162*)&d_Yh[((size_t)b * NN + q + 8) * CI + c] = h;
      *(__nv_bfloat162*)&d_Yl[((size_t)b * NN + q + 8) * CI + c] = l;
    }
  }
}

// ---------------------------------------------------------------------------
// wconv: WY[o][n] = W_w @ Y^T + W_b, + BN stats. grid (32 n, 2 o, 8 b)
// ---------------------------------------------------------------------------
__global__ __launch_bounds__(256) void wconv_mma_kernel(const float* __restrict__ Wb) {
  MMA_PROLOGUE
  __shared__ float s_sum[128];
  __shared__ float s_sq[128];
  const int b = blockIdx.z, n0 = blockIdx.x * 128, o0 = blockIdx.y * 128;
  if (tid < 128) { s_sum[tid] = 0.f; s_sq[tid] = 0.f; }
  mma_pipeline<2>(d_WWh + (size_t)o0 * CI, d_WWl + (size_t)o0 * CI,
                  d_Yh + ((size_t)b * NN + n0) * CI, d_Yl + ((size_t)b * NN + n0) * CI,
                  CI, CI, sb, tid, wm, wn, lane, C);
  const int orow0 = wm * 32 + (lane >> 2);
  const int nbase = n0 + wn * 64 + (lane & 3) * 2;
  float ls[2][2] = {}, lq[2][2] = {};
  float* WYb = d_WY + (size_t)b * CC * NN;
#pragma unroll
  for (int mi = 0; mi < 2; mi++) {
    int o = o0 + orow0 + mi * 16;
    float bias0 = Wb[o], bias8 = Wb[o + 8];
#pragma unroll
    for (int nj = 0; nj < 8; nj++) {
      int n = nbase + nj * 8;
      float v0 = C[mi][nj][0] + bias0, v1 = C[mi][nj][1] + bias0;
      float v2 = C[mi][nj][2] + bias8, v3 = C[mi][nj][3] + bias8;
      ls[mi][0] += v0 + v1;
      lq[mi][0] += v0 * v0 + v1 * v1;
      ls[mi][1] += v2 + v3;
      lq[mi][1] += v2 * v2 + v3 * v3;
      *(float2*)&WYb[(size_t)o * NN + n] = make_float2(v0, v1);
      *(float2*)&WYb[(size_t)(o + 8) * NN + n] = make_float2(v2, v3);
    }
  }
#pragma unroll
  for (int mi = 0; mi < 2; mi++)
#pragma unroll
    for (int h = 0; h < 2; h++) {
      int orow = orow0 + mi * 16 + h * 8;
      atomicAdd(&s_sum[orow], ls[mi][h]);
      atomicAdd(&s_sq[orow], lq[mi][h]);
    }
  __syncthreads();
  if (tid < 128) {
    atomicAdd(&d_sum[o0 + tid], (double)s_sum[tid]);
    atomicAdd(&d_sq[o0 + tid], (double)s_sq[tid]);
  }
}

// ---------------------------------------------------------------------------
// BN finalize
// ---------------------------------------------------------------------------
__global__ void bnprep_kernel(const float* __restrict__ gamma,
                              const float* __restrict__ beta) {
  int o = threadIdx.x;
  double cnt = (double)BB * (double)NN;
  double mean = d_sum[o] / cnt;
  double var = d_sq[o] / cnt - mean * mean;
  float sc = gamma[o] * rsqrtf((float)var + BN_EPS);
  d_scale[o] = sc;
  d_shift[o] = beta[o] - (float)mean * sc;
}

// ---------------------------------------------------------------------------
// final: out = WY*scale + shift + x
// ---------------------------------------------------------------------------
__global__ __launch_bounds__(256) void final_kernel(const float* __restrict__ x,
                                                    float* __restrict__ out) {
  size_t i4 = (size_t)blockIdx.x * 256 + threadIdx.x;
  int o = (int)((i4 >> 10) & 255);
  float sc = d_scale[o], sh = d_shift[o];
  float4 w = ((const float4*)d_WY)[i4];
  float4 xi = ((const float4*)x)[i4];
  float4 r;
  r.x = w.x * sc + sh + xi.x;
  r.y = w.y * sc + sh + xi.y;
  r.z = w.z * sc + sh + xi.z;
  r.w = w.w * sc + sh + xi.w;
  ((float4*)out)[i4] = r;
}

// ---------------------------------------------------------------------------
// launch
// ---------------------------------------------------------------------------
extern "C" void kernel_launch(void* const* d_in, const int* in_sizes, int n_in,
                              void* d_out, int out_size) {
  const float* x  = (const float*)d_in[0];
  const float* tw = (const float*)d_in[1];
  const float* tb = (const float*)d_in[2];
  const float* pw = (const float*)d_in[3];
  const float* pb = (const float*)d_in[4];
  const float* gw = (const float*)d_in[5];
  const float* gb = (const float*)d_in[6];
  const float* Ww = (const float*)d_in[7];
  const float* Wb = (const float*)d_in[8];
  const float* bg = (const float*)d_in[9];
  const float* bb = (const float*)d_in[10];
  float* out = (float*)d_out;

  cudaFuncSetAttribute(conv_fused_kernel, cudaFuncAttributeMaxDynamicSharedMemorySize, DSMEM_BYTES);
  cudaFuncSetAttribute(attn_kernel, cudaFuncAttributeMaxDynamicSharedMemorySize, ATTN_SMEM);
  cudaFuncSetAttribute(wconv_mma_kernel, cudaFuncAttributeMaxDynamicSharedMemorySize, DSMEM_BYTES);

  init_kernel<<<512, 256>>>(tw, tb, pw, pb, gw, gb, Ww);
  xsplit_kernel<<<dim3(128, 8, BB), dim3(32, 32)>>>(x);
  conv_fused_kernel<<<dim3(32, 3, BB), 256, DSMEM_BYTES>>>();
  pool_kernel<<<(2 * BB * MM * CI) / 256, 256>>>();
  attn_kernel<<<dim3(32, 1, BB), 256, ATTN_SMEM>>>();
  wconv_mma_kernel<<<dim3(32, 2, BB), 256, DSMEM_BYTES>>>(Wb);
  bnprep_kernel<<<1, 256>>>(bg, bb);
  final_kernel<<<(BB * CC * NN / 4) / 256, 256>>>(x, out);
}